// round 15
// baseline (speedup 1.0000x reference)
#include <cuda_runtime.h>
#include <cuda_fp16.h>
#include <math.h>
#include <cstdint>

// Problem constants
#define EMB    2048
#define HEADS  16
#define HEADD  128
#define BATCH  4
#define SEQ    2048
#define MROWS  (BATCH * SEQ)        // 8192
#define KDIM   EMB

// ---------------------------------------------------------------------------
// Scratch (device globals: allocation-free)
// ---------------------------------------------------------------------------
__device__ __half g_xh[(size_t)MROWS * EMB];   // X fp16 (reused as ctx)
__device__ __half g_w[4][(size_t)EMB * EMB];   // Wq,Wk,Wv,Wo (fp16)
__device__ __half g_qh[(size_t)MROWS * EMB];   // [B,S,H,D] row-major
__device__ __half g_kh[(size_t)MROWS * EMB];
__device__ __half g_vh[(size_t)MROWS * EMB];

// ---------------------------------------------------------------------------
// PTX helpers (compute_103-safe: no 'a' features)
// ---------------------------------------------------------------------------
__device__ __forceinline__ uint32_t smem_u32(const void* p) {
    uint32_t a;
    asm("{ .reg .u64 t; cvta.to.shared.u64 t, %1; cvt.u32.u64 %0, t; }" : "=r"(a) : "l"(p));
    return a;
}

#define CP_ASYNC16(dst, src) \
    asm volatile("cp.async.cg.shared.global [%0], [%1], 16;" :: "r"(dst), "l"(src) : "memory")
#define CP_COMMIT() asm volatile("cp.async.commit_group;" ::: "memory")
#define CP_WAIT1()  asm volatile("cp.async.wait_group 1;" ::: "memory")

#define LDSM4(r, a)                                                              \
    asm volatile("ldmatrix.sync.aligned.m8n8.x4.shared.b16 {%0,%1,%2,%3}, [%4];" \
        : "=r"((r)[0]), "=r"((r)[1]), "=r"((r)[2]), "=r"((r)[3]) : "r"(a))

#define LDSM4T(r, a)                                                                   \
    asm volatile("ldmatrix.sync.aligned.m8n8.x4.trans.shared.b16 {%0,%1,%2,%3}, [%4];" \
        : "=r"((r)[0]), "=r"((r)[1]), "=r"((r)[2]), "=r"((r)[3]) : "r"(a))

// Non-volatile: pure register op; "+f" accumulator constraints preserve
// per-element ordering while letting ptxas schedule.
#define MMA16816(d, a, b0, b1)                                                   \
    asm("mma.sync.aligned.m16n8k16.row.col.f32.f16.f16.f32 "                     \
        "{%0,%1,%2,%3}, {%4,%5,%6,%7}, {%8,%9}, {%0,%1,%2,%3};"                  \
        : "+f"((d)[0]), "+f"((d)[1]), "+f"((d)[2]), "+f"((d)[3])                  \
        : "r"((a)[0]), "r"((a)[1]), "r"((a)[2]), "r"((a)[3]), "r"(b0), "r"(b1))

// Swizzled byte offset within a [rows][32] fp16 tile (64B rows, 4 x 16B units)
__device__ __forceinline__ uint32_t sw_off(int row, int unit) {
    return (uint32_t)(row * 64) + ((uint32_t)(unit ^ ((row >> 1) & 3)) << 4);
}

__device__ __forceinline__ uint32_t pack_h2(float a, float b) {
    __half2 t = __floats2half2_rn(a, b);
    return *reinterpret_cast<uint32_t*>(&t);
}

// ---------------------------------------------------------------------------
// fp32 -> fp16 convert (vectorized x4)
// ---------------------------------------------------------------------------
__global__ void conv_f16(const float* __restrict__ in, __half* __restrict__ hi, int n4)
{
    int i = blockIdx.x * blockDim.x + threadIdx.x;
    if (i >= n4) return;
    float4 v = ((const float4*)in)[i];
    __half2* hp = (__half2*)hi;
    hp[2 * i]     = __floats2half2_rn(v.x, v.y);
    hp[2 * i + 1] = __floats2half2_rn(v.z, v.w);
}

// fp32 -> fp16: all four weight matrices in one launch
__global__ void conv4_f16(const float* __restrict__ w0, const float* __restrict__ w1,
                          const float* __restrict__ w2, const float* __restrict__ w3,
                          __half* __restrict__ out, int n4each)
{
    int i = blockIdx.x * blockDim.x + threadIdx.x;
    if (i >= 4 * n4each) return;
    int which = i / n4each;
    int j = i - which * n4each;
    const float* src = (which == 0) ? w0 : (which == 1) ? w1 : (which == 2) ? w2 : w3;
    float4 v = ((const float4*)src)[j];
    __half2* hp = (__half2*)(out + (size_t)which * EMB * EMB);
    hp[2 * j]     = __floats2half2_rn(v.x, v.y);
    hp[2 * j + 1] = __floats2half2_rn(v.z, v.w);
}

// ---------------------------------------------------------------------------
// fp16 mma.sync GEMM mainloop. CTA 128x128, K-chunk 64 (two 128x32 subtiles
// per operand), 3 stages (97 KB -> 2 CTAs/SM, 16 warps), 32 barriers/GEMM
// (half of before). 8 warps as 4(m) x 2(n) -> warp tile 32x64.
// ---------------------------------------------------------------------------
#define SUBT_B    8192                  // one 128x32 fp16 subtile
#define STAGE_B2  (4 * SUBT_B)          // A0,A1,B0,B1 = 32 KB
#define NSTAGE    3
#define GEMM_DSMEM (NSTAGE * STAGE_B2 + 1024)   // ~97 KB
#define NCHUNK    (KDIM / 64)           // 32

__device__ __forceinline__ void load_stage(
    const __half* __restrict__ Ah, const __half* __restrict__ Bh,
    int m0, int n0, int kc, uint32_t sbase, int tid)
{
    const int unit  = tid & 3;
    const int rbase = tid >> 2;          // 0..63
#pragma unroll
    for (int sub = 0; sub < 2; sub++) {
#pragma unroll
        for (int p = 0; p < 2; p++) {
            const int row = rbase + p * 64;
            const uint32_t so = (uint32_t)sub * SUBT_B + sw_off(row, unit);
            const size_t ga = (size_t)(m0 + row) * KDIM + kc + sub * 32 + unit * 8;
            const size_t gb = (size_t)(n0 + row) * KDIM + kc + sub * 32 + unit * 8;
            CP_ASYNC16(sbase + so,               Ah + ga);
            CP_ASYNC16(sbase + 2 * SUBT_B + so,  Bh + gb);
        }
    }
}

__device__ __forceinline__ void gemm_mainloop(
    const __half* __restrict__ Ah, const __half* __restrict__ Bh,
    int m0, int n0, uint32_t base, int tid, float acc[2][8][4])
{
    const int lane = tid & 31;
    const int w    = tid >> 5;
    const int wm   = (w & 3) * 32;       // warp m offset
    const int wn   = (w >> 2) * 64;      // warp n offset

    const int r8   = lane & 7;
    const int mat  = lane >> 3;
    const int lrow = ((mat & 1) << 3) + r8;
    const int lch  = mat >> 1;

#pragma unroll
    for (int i = 0; i < 2; i++)
#pragma unroll
        for (int j = 0; j < 8; j++)
#pragma unroll
            for (int c = 0; c < 4; c++) acc[i][j][c] = 0.0f;

    load_stage(Ah, Bh, m0, n0, 0,  base,            tid); CP_COMMIT();
    load_stage(Ah, Bh, m0, n0, 64, base + STAGE_B2, tid); CP_COMMIT();

    for (int i = 0; i < NCHUNK; i++) {
        const uint32_t sb = base + (uint32_t)(i % NSTAGE) * STAGE_B2;
        CP_WAIT1();
        __syncthreads();
        if (i + 2 < NCHUNK)
            load_stage(Ah, Bh, m0, n0, (i + 2) * 64,
                       base + (uint32_t)((i + 2) % NSTAGE) * STAGE_B2, tid);
        CP_COMMIT();

#pragma unroll
        for (int ks = 0; ks < 4; ks++) {
            const uint32_t sAh = sb + (uint32_t)(ks >> 1) * SUBT_B;
            const uint32_t sBh = sb + 2 * SUBT_B + (uint32_t)(ks >> 1) * SUBT_B;
            const int u = (ks & 1) * 2 + lch;
            uint32_t ah[2][4], bh[4][4];
#pragma unroll
            for (int mi = 0; mi < 2; mi++)
                LDSM4(ah[mi], sAh + sw_off(wm + mi * 16 + lrow, u));
#pragma unroll
            for (int g = 0; g < 4; g++)
                LDSM4(bh[g], sBh + sw_off(wn + g * 16 + lrow, u));
#pragma unroll
            for (int mi = 0; mi < 2; mi++)
#pragma unroll
                for (int g = 0; g < 4; g++)
#pragma unroll
                    for (int h = 0; h < 2; h++)
                        MMA16816(acc[mi][g * 2 + h], ah[mi], bh[g][h], bh[g][2 + h]);
        }
    }
}

// Fused QKV projection: blockIdx.z selects {Wq->q (scaled), Wk->k, Wv->v}
__global__ __launch_bounds__(256, 2)
void gemm_qkv(const __half* __restrict__ Ah,
              const __half* __restrict__ Wbase,
              const float* __restrict__ bq, const float* __restrict__ bk,
              const float* __restrict__ bv,
              __half* __restrict__ qh, __half* __restrict__ kh,
              __half* __restrict__ vh)
{
    extern __shared__ char dyn[];
    const int tid = threadIdx.x;
    const int z   = blockIdx.z;
    const int m0  = blockIdx.y * 128;
    const int n0  = blockIdx.x * 128;
    const uint32_t base = (smem_u32(dyn) + 1023u) & ~1023u;

    const __half* Bh = Wbase + (size_t)z * EMB * EMB;
    const float* bias = (z == 0) ? bq : (z == 1) ? bk : bv;
    const float scale = (z == 0) ? 0.08838834764831845f : 1.0f;

    float acc[2][8][4];
    gemm_mainloop(Ah, Bh, m0, n0, base, tid, acc);

    const int lane = tid & 31;
    const int w    = tid >> 5;
    const int wm   = (w & 3) * 32;
    const int wn   = (w >> 2) * 64;
    const int qr   = lane >> 2;
    const int qc   = (lane & 3) * 2;

    __half* dst = (z == 0) ? qh : (z == 1) ? kh : vh;

#pragma unroll
    for (int mi = 0; mi < 2; mi++) {
#pragma unroll
        for (int nj = 0; nj < 8; nj++) {
            const int col = n0 + wn + nj * 8 + qc;
            const float2 bb = *(const float2*)&bias[col];
            const int row0 = m0 + wm + mi * 16 + qr;
            float v00 = (acc[mi][nj][0] + bb.x) * scale;
            float v01 = (acc[mi][nj][1] + bb.y) * scale;
            float v10 = (acc[mi][nj][2] + bb.x) * scale;
            float v11 = (acc[mi][nj][3] + bb.y) * scale;
            *(__half2*)(dst + (size_t)row0 * EMB + col)       = __floats2half2_rn(v00, v01);
            *(__half2*)(dst + (size_t)(row0 + 8) * EMB + col) = __floats2half2_rn(v10, v11);
        }
    }
}

// Output projection: fp32 out + bias
__global__ __launch_bounds__(256, 2)
void gemm_oproj(const __half* __restrict__ Ah,
                const __half* __restrict__ Bh,
                const float* __restrict__ bias, float* __restrict__ Cf)
{
    extern __shared__ char dyn[];
    const int tid = threadIdx.x;
    const int m0  = blockIdx.y * 128;
    const int n0  = blockIdx.x * 128;
    const uint32_t base = (smem_u32(dyn) + 1023u) & ~1023u;

    float acc[2][8][4];
    gemm_mainloop(Ah, Bh, m0, n0, base, tid, acc);

    const int lane = tid & 31;
    const int w    = tid >> 5;
    const int wm   = (w & 3) * 32;
    const int wn   = (w >> 2) * 64;
    const int qr   = lane >> 2;
    const int qc   = (lane & 3) * 2;

#pragma unroll
    for (int mi = 0; mi < 2; mi++) {
#pragma unroll
        for (int nj = 0; nj < 8; nj++) {
            const int col = n0 + wn + nj * 8 + qc;
            const float2 bb = *(const float2*)&bias[col];
            const int row0 = m0 + wm + mi * 16 + qr;
            *(float2*)&Cf[(size_t)row0 * EMB + col] =
                make_float2(acc[mi][nj][0] + bb.x, acc[mi][nj][1] + bb.y);
            *(float2*)&Cf[(size_t)(row0 + 8) * EMB + col] =
                make_float2(acc[mi][nj][2] + bb.x, acc[mi][nj][3] + bb.y);
        }
    }
}

// ---------------------------------------------------------------------------
// Tensor-core flash attention, fp16 operands / fp32 accum, causal.
// 1/sqrt(d) pre-folded into Q. 128 threads (4 warps), Q-tile 64, KV-tile 64,
// 2-buffer KV ring, 80 KB smem -> 2 CTAs/SM. Q fragments cached in registers
// across the whole KV loop (loaded once at kb=0).
// ---------------------------------------------------------------------------
#define FL_THREADS 128
#define FL_QTILE_B 16384                // 64 rows x 128 cols fp16
#define FL_KVBUF_B 32768                // Kh 16KB + Vh 16KB
#define FL_SMEM (FL_QTILE_B + 2 * FL_KVBUF_B)   // 80 KB

__global__ __launch_bounds__(FL_THREADS, 2)
void flash_f16(const __half* __restrict__ qh,
               const __half* __restrict__ kh, const __half* __restrict__ vh,
               __half* __restrict__ cth)
{
    extern __shared__ char smf[];
    const int tid  = threadIdx.x;
    const int lane = tid & 31;
    const int w    = tid >> 5;           // 0..3
    const int wm16 = w * 16;

    const int bx  = gridDim.x - 1 - blockIdx.x;   // heavy blocks first
    const int q0  = bx * 64;
    const int bh_ = blockIdx.y;
    const int bb  = bh_ >> 4;
    const int hh  = bh_ & 15;
    const int hcol = hh * 128;
    const int nkb = bx + 1;

    const uint32_t sQh = smem_u32(smf);
    const uint32_t sKV = sQh + FL_QTILE_B;   // buf b: Kh @ +0, Vh @ +16384

    const int r8   = lane & 7;
    const int mat  = lane >> 3;
    const int lrow = ((mat & 1) << 3) + r8;
    const int lch  = mat >> 1;
    const int tkrow = (lane & 7) + ((lane >> 4) << 3);
    const int tdh   = ((lane >> 3) & 1) << 3;
    const int t4 = lane & 3;
    const int gr = lane >> 2;

    // Prologue: Q (64 rows) + KV block 0 -> slot 0
    {
        const int unit = tid & 3;
        const int rr   = tid >> 2;       // 0..31
#pragma unroll
        for (int p = 0; p < 2; p++) {
            const int row = rr + p * 32;
            const size_t grow = (size_t)(bb * SEQ + q0 + row) * EMB + hcol + unit * 8;
#pragma unroll
            for (int c4 = 0; c4 < 4; c4++) {
                const uint32_t so = (uint32_t)c4 * 4096 + sw_off(row, unit);
                CP_ASYNC16(sQh + so, qh + grow + c4 * 32);
            }
        }
#pragma unroll
        for (int p = 0; p < 2; p++) {
            const int row = rr + p * 32;
            const size_t g0 = (size_t)(bb * SEQ + row) * EMB + hcol + unit * 8;
#pragma unroll
            for (int c4 = 0; c4 < 4; c4++) {
                const uint32_t so = (uint32_t)c4 * 4096 + sw_off(row, unit);
                CP_ASYNC16(sKV + so,         kh + g0 + c4 * 32);
                CP_ASYNC16(sKV + 16384 + so, vh + g0 + c4 * 32);
            }
        }
        CP_COMMIT();
    }

    float o[16][4];
#pragma unroll
    for (int j = 0; j < 16; j++)
#pragma unroll
        for (int c = 0; c < 4; c++) o[j][c] = 0.0f;
    float m0 = -1e30f, m1 = -1e30f, l0 = 0.0f, l1 = 0.0f;

    uint32_t qa[8][4];                   // Q fragments, loop-invariant

    for (int kb = 0; kb < nkb; kb++) {
        const uint32_t buf = sKV + (uint32_t)(kb & 1) * FL_KVBUF_B;

        if (kb + 1 < nkb) {
            const uint32_t nbuf = sKV + (uint32_t)((kb + 1) & 1) * FL_KVBUF_B;
            const int unit = tid & 3;
            const int rr   = tid >> 2;
#pragma unroll
            for (int p = 0; p < 2; p++) {
                const int row = rr + p * 32;
                const size_t grow = (size_t)(bb * SEQ + (kb + 1) * 64 + row) * EMB + hcol + unit * 8;
#pragma unroll
                for (int c4 = 0; c4 < 4; c4++) {
                    const uint32_t so = (uint32_t)c4 * 4096 + sw_off(row, unit);
                    CP_ASYNC16(nbuf + so,         kh + grow + c4 * 32);
                    CP_ASYNC16(nbuf + 16384 + so, vh + grow + c4 * 32);
                }
            }
        }
        CP_COMMIT();
        CP_WAIT1();
        __syncthreads();

        if (kb == 0) {
            // Load Q fragments once; reused for the entire KV loop.
#pragma unroll
            for (int ks = 0; ks < 8; ks++) {
                const uint32_t qoff = (uint32_t)(ks >> 1) * 4096 +
                                      sw_off(wm16 + lrow, (ks & 1) * 2 + lch);
                LDSM4(qa[ks], sQh + qoff);
            }
        }

        {
            float s[8][4];
#pragma unroll
            for (int j = 0; j < 8; j++)
#pragma unroll
                for (int c = 0; c < 4; c++) s[j][c] = 0.0f;

            // ---- S = Q K^T (fp16, Q frags cached) ----
#pragma unroll
            for (int ks = 0; ks < 8; ks++) {
                uint32_t kbh[4][4];
#pragma unroll
                for (int g = 0; g < 4; g++) {
                    const uint32_t koff = (uint32_t)(ks >> 1) * 4096 +
                                          sw_off(g * 16 + lrow, (ks & 1) * 2 + lch);
                    LDSM4(kbh[g], buf + koff);
                }
#pragma unroll
                for (int g = 0; g < 4; g++)
#pragma unroll
                    for (int h = 0; h < 2; h++)
                        MMA16816(s[g * 2 + h], qa[ks], kbh[g][h], kbh[g][2 + h]);
            }

            // causal mask (scale already folded into Q)
            if (kb * 64 + 63 > q0 + wm16) {
                const int row0 = q0 + wm16 + gr;
#pragma unroll
                for (int j = 0; j < 8; j++) {
                    const int col = kb * 64 + (j >> 1) * 16 + (j & 1) * 8 + 2 * t4;
                    if (col > row0)         s[j][0] = -1e30f;
                    if (col + 1 > row0)     s[j][1] = -1e30f;
                    if (col > row0 + 8)     s[j][2] = -1e30f;
                    if (col + 1 > row0 + 8) s[j][3] = -1e30f;
                }
            }

            // ---- online softmax ----
            float mx0 = -1e30f, mx1 = -1e30f;
#pragma unroll
            for (int j = 0; j < 8; j++) {
                mx0 = fmaxf(mx0, fmaxf(s[j][0], s[j][1]));
                mx1 = fmaxf(mx1, fmaxf(s[j][2], s[j][3]));
            }
            mx0 = fmaxf(mx0, __shfl_xor_sync(0xffffffffu, mx0, 1));
            mx0 = fmaxf(mx0, __shfl_xor_sync(0xffffffffu, mx0, 2));
            mx1 = fmaxf(mx1, __shfl_xor_sync(0xffffffffu, mx1, 1));
            mx1 = fmaxf(mx1, __shfl_xor_sync(0xffffffffu, mx1, 2));

            const float mn0 = fmaxf(m0, mx0), mn1 = fmaxf(m1, mx1);
            const float a0 = __expf(m0 - mn0), a1 = __expf(m1 - mn1);
            m0 = mn0; m1 = mn1;

            float rs0 = 0.0f, rs1 = 0.0f;
#pragma unroll
            for (int j = 0; j < 8; j++) {
                s[j][0] = __expf(s[j][0] - mn0); rs0 += s[j][0];
                s[j][1] = __expf(s[j][1] - mn0); rs0 += s[j][1];
                s[j][2] = __expf(s[j][2] - mn1); rs1 += s[j][2];
                s[j][3] = __expf(s[j][3] - mn1); rs1 += s[j][3];
            }
            rs0 += __shfl_xor_sync(0xffffffffu, rs0, 1);
            rs0 += __shfl_xor_sync(0xffffffffu, rs0, 2);
            rs1 += __shfl_xor_sync(0xffffffffu, rs1, 1);
            rs1 += __shfl_xor_sync(0xffffffffu, rs1, 2);
            l0 = l0 * a0 + rs0;
            l1 = l1 * a1 + rs1;

#pragma unroll
            for (int j = 0; j < 16; j++) {
                o[j][0] *= a0; o[j][1] *= a0;
                o[j][2] *= a1; o[j][3] *= a1;
            }

            // ---- O += P V (fp16 P) ----
#pragma unroll
            for (int kk = 0; kk < 4; kk++) {
                const float* sA = s[2 * kk];
                const float* sB = s[2 * kk + 1];
                uint32_t pa_h[4];
                pa_h[0] = pack_h2(sA[0], sA[1]);
                pa_h[1] = pack_h2(sA[2], sA[3]);
                pa_h[2] = pack_h2(sB[0], sB[1]);
                pa_h[3] = pack_h2(sB[2], sB[3]);
                const int vkrow = kk * 16 + tkrow;
#pragma unroll
                for (int gp = 0; gp < 4; gp++) {
                    uint32_t vbh[2][4];
#pragma unroll
                    for (int i2 = 0; i2 < 2; i2++) {
                        const int dcol = (gp * 2 + i2) * 16 + tdh;
                        const uint32_t voff = (uint32_t)(dcol >> 5) * 4096 +
                                              sw_off(vkrow, (dcol >> 3) & 3);
                        LDSM4T(vbh[i2], buf + 16384 + voff);
                    }
#pragma unroll
                    for (int i2 = 0; i2 < 2; i2++)
#pragma unroll
                        for (int h = 0; h < 2; h++)
                            MMA16816(o[(gp * 2 + i2) * 2 + h], pa_h,
                                     vbh[i2][h], vbh[i2][2 + h]);
                }
            }
        }
        __syncthreads();   // all warps done reading slot kb&1 before overwrite
    }

    // Epilogue: ctx = O / l, fp16, [B,S,E] row-major
    const float inv0 = 1.0f / l0, inv1 = 1.0f / l1;
    const int row0 = q0 + wm16 + gr;
    const size_t base0 = (size_t)(bb * SEQ + row0) * EMB + hcol;
    const size_t base1 = base0 + (size_t)8 * EMB;
#pragma unroll
    for (int j = 0; j < 16; j++) {
        const int d0 = j * 8 + 2 * t4;
        *(__half2*)(cth + base0 + d0) = __floats2half2_rn(o[j][0] * inv0, o[j][1] * inv0);
        *(__half2*)(cth + base1 + d0) = __floats2half2_rn(o[j][2] * inv1, o[j][3] * inv1);
    }
}

// ---------------------------------------------------------------------------
extern "C" void kernel_launch(void* const* d_in, const int* in_sizes, int n_in,
                              void* d_out, int out_size)
{
    const float* x  = (const float*)d_in[0];
    const float* Wq = (const float*)d_in[2];
    const float* bq = (const float*)d_in[3];
    const float* Wk = (const float*)d_in[4];
    const float* bk = (const float*)d_in[5];
    const float* Wv = (const float*)d_in[6];
    const float* bv = (const float*)d_in[7];
    const float* Wo = (const float*)d_in[8];
    const float* bo = (const float*)d_in[9];
    float* out = (float*)d_out;

    __half *xh, *wp, *qh, *kh, *vh;
    cudaGetSymbolAddress((void**)&xh, g_xh);
    cudaGetSymbolAddress((void**)&wp, g_w);
    cudaGetSymbolAddress((void**)&qh, g_qh);
    cudaGetSymbolAddress((void**)&kh, g_kh);
    cudaGetSymbolAddress((void**)&vh, g_vh);

    const int nX4 = MROWS * EMB / 4;
    const int nW4 = EMB * EMB / 4;

    conv_f16<<<(nX4 + 255) / 256, 256>>>(x, xh, nX4);
    conv4_f16<<<(4 * nW4 + 255) / 256, 256>>>(Wq, Wk, Wv, Wo, wp, nW4);

    cudaFuncSetAttribute(gemm_qkv, cudaFuncAttributeMaxDynamicSharedMemorySize,
                         GEMM_DSMEM);
    cudaFuncSetAttribute(gemm_oproj, cudaFuncAttributeMaxDynamicSharedMemorySize,
                         GEMM_DSMEM);

    // Fused QKV: grid.z = 3 selects projection; CTA tile 128x128
    gemm_qkv<<<dim3(EMB / 128, MROWS / 128, 3), 256, GEMM_DSMEM>>>(
        xh, wp, bq, bk, bv, qh, kh, vh);

    cudaFuncSetAttribute(flash_f16, cudaFuncAttributeMaxDynamicSharedMemorySize,
                         FL_SMEM);
    // flash writes ctx (fp16) into xh (X dead after QKV GEMMs)
    flash_f16<<<dim3(SEQ / 64, BATCH * HEADS), FL_THREADS, FL_SMEM>>>(
        qh, kh, vh, xh);

    gemm_oproj<<<dim3(EMB / 128, MROWS / 128), 256, GEMM_DSMEM>>>(
        xh, wp + 3 * (size_t)EMB * EMB, bo, out);
}

// round 16
// speedup vs baseline: 1.0162x; 1.0162x over previous
#include <cuda_runtime.h>
#include <cuda_fp16.h>
#include <math.h>
#include <cstdint>

// Problem constants
#define EMB    2048
#define HEADS  16
#define HEADD  128
#define BATCH  4
#define SEQ    2048
#define MROWS  (BATCH * SEQ)        // 8192
#define KDIM   EMB

// ---------------------------------------------------------------------------
// Scratch (device globals: allocation-free)
// ---------------------------------------------------------------------------
__device__ __half g_xh[(size_t)MROWS * EMB];   // X fp16 (reused as ctx)
__device__ __half g_w[4][(size_t)EMB * EMB];   // Wq,Wk,Wv,Wo (fp16)
__device__ __half g_qh[(size_t)MROWS * EMB];   // [B,S,H,D] row-major
__device__ __half g_kh[(size_t)MROWS * EMB];
__device__ __half g_vh[(size_t)MROWS * EMB];

// ---------------------------------------------------------------------------
// PTX helpers (compute_103-safe: no 'a' features)
// ---------------------------------------------------------------------------
__device__ __forceinline__ uint32_t smem_u32(const void* p) {
    uint32_t a;
    asm("{ .reg .u64 t; cvta.to.shared.u64 t, %1; cvt.u32.u64 %0, t; }" : "=r"(a) : "l"(p));
    return a;
}

#define CP_ASYNC16(dst, src) \
    asm volatile("cp.async.cg.shared.global [%0], [%1], 16;" :: "r"(dst), "l"(src) : "memory")
#define CP_COMMIT() asm volatile("cp.async.commit_group;" ::: "memory")
#define CP_WAIT1()  asm volatile("cp.async.wait_group 1;" ::: "memory")

#define LDSM4(r, a)                                                              \
    asm volatile("ldmatrix.sync.aligned.m8n8.x4.shared.b16 {%0,%1,%2,%3}, [%4];" \
        : "=r"((r)[0]), "=r"((r)[1]), "=r"((r)[2]), "=r"((r)[3]) : "r"(a))

#define LDSM4T(r, a)                                                                   \
    asm volatile("ldmatrix.sync.aligned.m8n8.x4.trans.shared.b16 {%0,%1,%2,%3}, [%4];" \
        : "=r"((r)[0]), "=r"((r)[1]), "=r"((r)[2]), "=r"((r)[3]) : "r"(a))

// Non-volatile: pure register op; "+f" accumulator constraints preserve
// per-element ordering while letting ptxas schedule.
#define MMA16816(d, a, b0, b1)                                                   \
    asm("mma.sync.aligned.m16n8k16.row.col.f32.f16.f16.f32 "                     \
        "{%0,%1,%2,%3}, {%4,%5,%6,%7}, {%8,%9}, {%0,%1,%2,%3};"                  \
        : "+f"((d)[0]), "+f"((d)[1]), "+f"((d)[2]), "+f"((d)[3])                  \
        : "r"((a)[0]), "r"((a)[1]), "r"((a)[2]), "r"((a)[3]), "r"(b0), "r"(b1))

// Swizzled byte offset within a [rows][32] fp16 tile (64B rows, 4 x 16B units)
__device__ __forceinline__ uint32_t sw_off(int row, int unit) {
    return (uint32_t)(row * 64) + ((uint32_t)(unit ^ ((row >> 1) & 3)) << 4);
}

__device__ __forceinline__ uint32_t pack_h2(float a, float b) {
    __half2 t = __floats2half2_rn(a, b);
    return *reinterpret_cast<uint32_t*>(&t);
}

// ---------------------------------------------------------------------------
// fp32 -> fp16 convert: X and all four weight matrices in ONE launch
// ---------------------------------------------------------------------------
__global__ void conv_all(const float* __restrict__ x,
                         const float* __restrict__ w0, const float* __restrict__ w1,
                         const float* __restrict__ w2, const float* __restrict__ w3,
                         __half* __restrict__ xh, __half* __restrict__ wp,
                         int nX4, int nW4)
{
    int i = blockIdx.x * blockDim.x + threadIdx.x;
    if (i < nX4) {
        float4 v = ((const float4*)x)[i];
        __half2* hp = (__half2*)xh;
        hp[2 * i]     = __floats2half2_rn(v.x, v.y);
        hp[2 * i + 1] = __floats2half2_rn(v.z, v.w);
        return;
    }
    int j = i - nX4;
    if (j >= 4 * nW4) return;
    int which = j / nW4;
    int k = j - which * nW4;
    const float* src = (which == 0) ? w0 : (which == 1) ? w1 : (which == 2) ? w2 : w3;
    float4 v = ((const float4*)src)[k];
    __half2* hp = (__half2*)(wp + (size_t)which * EMB * EMB);
    hp[2 * k]     = __floats2half2_rn(v.x, v.y);
    hp[2 * k + 1] = __floats2half2_rn(v.z, v.w);
}

// ---------------------------------------------------------------------------
// fp16 mma.sync GEMM mainloop. CTA 128x128, K-chunk 64 (two 128x32 subtiles
// per operand), 3 stages (97 KB -> 2 CTAs/SM, 16 warps).
// 8 warps as 4(m) x 2(n) -> warp tile 32x64.
// ---------------------------------------------------------------------------
#define SUBT_B    8192                  // one 128x32 fp16 subtile
#define STAGE_B2  (4 * SUBT_B)          // A0,A1,B0,B1 = 32 KB
#define NSTAGE    3
#define GEMM_DSMEM (NSTAGE * STAGE_B2 + 1024)   // ~97 KB
#define NCHUNK    (KDIM / 64)           // 32

__device__ __forceinline__ void load_stage(
    const __half* __restrict__ Ah, const __half* __restrict__ Bh,
    int m0, int n0, int kc, uint32_t sbase, int tid)
{
    const int unit  = tid & 3;
    const int rbase = tid >> 2;          // 0..63
#pragma unroll
    for (int sub = 0; sub < 2; sub++) {
#pragma unroll
        for (int p = 0; p < 2; p++) {
            const int row = rbase + p * 64;
            const uint32_t so = (uint32_t)sub * SUBT_B + sw_off(row, unit);
            const size_t ga = (size_t)(m0 + row) * KDIM + kc + sub * 32 + unit * 8;
            const size_t gb = (size_t)(n0 + row) * KDIM + kc + sub * 32 + unit * 8;
            CP_ASYNC16(sbase + so,               Ah + ga);
            CP_ASYNC16(sbase + 2 * SUBT_B + so,  Bh + gb);
        }
    }
}

__device__ __forceinline__ void gemm_mainloop(
    const __half* __restrict__ Ah, const __half* __restrict__ Bh,
    int m0, int n0, uint32_t base, int tid, float acc[2][8][4])
{
    const int lane = tid & 31;
    const int w    = tid >> 5;
    const int wm   = (w & 3) * 32;       // warp m offset
    const int wn   = (w >> 2) * 64;      // warp n offset

    const int r8   = lane & 7;
    const int mat  = lane >> 3;
    const int lrow = ((mat & 1) << 3) + r8;
    const int lch  = mat >> 1;

#pragma unroll
    for (int i = 0; i < 2; i++)
#pragma unroll
        for (int j = 0; j < 8; j++)
#pragma unroll
            for (int c = 0; c < 4; c++) acc[i][j][c] = 0.0f;

    load_stage(Ah, Bh, m0, n0, 0,  base,            tid); CP_COMMIT();
    load_stage(Ah, Bh, m0, n0, 64, base + STAGE_B2, tid); CP_COMMIT();

    for (int i = 0; i < NCHUNK; i++) {
        const uint32_t sb = base + (uint32_t)(i % NSTAGE) * STAGE_B2;
        CP_WAIT1();
        __syncthreads();
        if (i + 2 < NCHUNK)
            load_stage(Ah, Bh, m0, n0, (i + 2) * 64,
                       base + (uint32_t)((i + 2) % NSTAGE) * STAGE_B2, tid);
        CP_COMMIT();

#pragma unroll
        for (int ks = 0; ks < 4; ks++) {
            const uint32_t sAh = sb + (uint32_t)(ks >> 1) * SUBT_B;
            const uint32_t sBh = sb + 2 * SUBT_B + (uint32_t)(ks >> 1) * SUBT_B;
            const int u = (ks & 1) * 2 + lch;
            uint32_t ah[2][4], bh[4][4];
#pragma unroll
            for (int mi = 0; mi < 2; mi++)
                LDSM4(ah[mi], sAh + sw_off(wm + mi * 16 + lrow, u));
#pragma unroll
            for (int g = 0; g < 4; g++)
                LDSM4(bh[g], sBh + sw_off(wn + g * 16 + lrow, u));
#pragma unroll
            for (int mi = 0; mi < 2; mi++)
#pragma unroll
                for (int g = 0; g < 4; g++)
#pragma unroll
                    for (int h = 0; h < 2; h++)
                        MMA16816(acc[mi][g * 2 + h], ah[mi], bh[g][h], bh[g][2 + h]);
        }
    }
}

// Fused QKV projection: blockIdx.z selects {Wq->q (scaled), Wk->k, Wv->v}
__global__ __launch_bounds__(256, 2)
void gemm_qkv(const __half* __restrict__ Ah,
              const __half* __restrict__ Wbase,
              const float* __restrict__ bq, const float* __restrict__ bk,
              const float* __restrict__ bv,
              __half* __restrict__ qh, __half* __restrict__ kh,
              __half* __restrict__ vh)
{
    extern __shared__ char dyn[];
    const int tid = threadIdx.x;
    const int z   = blockIdx.z;
    const int m0  = blockIdx.y * 128;
    const int n0  = blockIdx.x * 128;
    const uint32_t base = (smem_u32(dyn) + 1023u) & ~1023u;

    const __half* Bh = Wbase + (size_t)z * EMB * EMB;
    const float* bias = (z == 0) ? bq : (z == 1) ? bk : bv;
    const float scale = (z == 0) ? 0.08838834764831845f : 1.0f;

    float acc[2][8][4];
    gemm_mainloop(Ah, Bh, m0, n0, base, tid, acc);

    const int lane = tid & 31;
    const int w    = tid >> 5;
    const int wm   = (w & 3) * 32;
    const int wn   = (w >> 2) * 64;
    const int qr   = lane >> 2;
    const int qc   = (lane & 3) * 2;

    __half* dst = (z == 0) ? qh : (z == 1) ? kh : vh;

#pragma unroll
    for (int mi = 0; mi < 2; mi++) {
#pragma unroll
        for (int nj = 0; nj < 8; nj++) {
            const int col = n0 + wn + nj * 8 + qc;
            const float2 bb = *(const float2*)&bias[col];
            const int row0 = m0 + wm + mi * 16 + qr;
            float v00 = (acc[mi][nj][0] + bb.x) * scale;
            float v01 = (acc[mi][nj][1] + bb.y) * scale;
            float v10 = (acc[mi][nj][2] + bb.x) * scale;
            float v11 = (acc[mi][nj][3] + bb.y) * scale;
            *(__half2*)(dst + (size_t)row0 * EMB + col)       = __floats2half2_rn(v00, v01);
            *(__half2*)(dst + (size_t)(row0 + 8) * EMB + col) = __floats2half2_rn(v10, v11);
        }
    }
}

// Output projection: fp32 out + bias
__global__ __launch_bounds__(256, 2)
void gemm_oproj(const __half* __restrict__ Ah,
                const __half* __restrict__ Bh,
                const float* __restrict__ bias, float* __restrict__ Cf)
{
    extern __shared__ char dyn[];
    const int tid = threadIdx.x;
    const int m0  = blockIdx.y * 128;
    const int n0  = blockIdx.x * 128;
    const uint32_t base = (smem_u32(dyn) + 1023u) & ~1023u;

    float acc[2][8][4];
    gemm_mainloop(Ah, Bh, m0, n0, base, tid, acc);

    const int lane = tid & 31;
    const int w    = tid >> 5;
    const int wm   = (w & 3) * 32;
    const int wn   = (w >> 2) * 64;
    const int qr   = lane >> 2;
    const int qc   = (lane & 3) * 2;

#pragma unroll
    for (int mi = 0; mi < 2; mi++) {
#pragma unroll
        for (int nj = 0; nj < 8; nj++) {
            const int col = n0 + wn + nj * 8 + qc;
            const float2 bb = *(const float2*)&bias[col];
            const int row0 = m0 + wm + mi * 16 + qr;
            *(float2*)&Cf[(size_t)row0 * EMB + col] =
                make_float2(acc[mi][nj][0] + bb.x, acc[mi][nj][1] + bb.y);
            *(float2*)&Cf[(size_t)(row0 + 8) * EMB + col] =
                make_float2(acc[mi][nj][2] + bb.x, acc[mi][nj][3] + bb.y);
        }
    }
}

// ---------------------------------------------------------------------------
// Tensor-core flash attention, fp16 operands / fp32 accum, causal.
// 1/sqrt(d) pre-folded into Q. 128 threads (4 warps), Q-tile 64, KV-tile 64.
// 3-slot KV ring -> SINGLE __syncthreads per iteration (slot written at iter
// kb was last read at iter kb-2; syncs at kb-1 and kb fence it).
// smem 112 KB -> 2 CTAs/SM (224 <= 228 KB).
// ---------------------------------------------------------------------------
#define FL_THREADS 128
#define FL_QTILE_B 16384                // 64 rows x 128 cols fp16
#define FL_KVBUF_B 32768                // Kh 16KB + Vh 16KB
#define FL_SMEM (FL_QTILE_B + 3 * FL_KVBUF_B)   // 112 KB

__global__ __launch_bounds__(FL_THREADS, 2)
void flash_f16(const __half* __restrict__ qh,
               const __half* __restrict__ kh, const __half* __restrict__ vh,
               __half* __restrict__ cth)
{
    extern __shared__ char smf[];
    const int tid  = threadIdx.x;
    const int lane = tid & 31;
    const int w    = tid >> 5;           // 0..3
    const int wm16 = w * 16;

    const int bx  = gridDim.x - 1 - blockIdx.x;   // heavy blocks first
    const int q0  = bx * 64;
    const int bh_ = blockIdx.y;
    const int bb  = bh_ >> 4;
    const int hh  = bh_ & 15;
    const int hcol = hh * 128;
    const int nkb = bx + 1;

    const uint32_t sQh = smem_u32(smf);
    const uint32_t sKV = sQh + FL_QTILE_B;   // ring slot b: Kh @ +0, Vh @ +16384

    const int r8   = lane & 7;
    const int mat  = lane >> 3;
    const int lrow = ((mat & 1) << 3) + r8;
    const int lch  = mat >> 1;
    const int tkrow = (lane & 7) + ((lane >> 4) << 3);
    const int tdh   = ((lane >> 3) & 1) << 3;
    const int t4 = lane & 3;
    const int gr = lane >> 2;

    // Prologue: Q (64 rows) + KV block 0 -> slot 0
    {
        const int unit = tid & 3;
        const int rr   = tid >> 2;       // 0..31
#pragma unroll
        for (int p = 0; p < 2; p++) {
            const int row = rr + p * 32;
            const size_t grow = (size_t)(bb * SEQ + q0 + row) * EMB + hcol + unit * 8;
#pragma unroll
            for (int c4 = 0; c4 < 4; c4++) {
                const uint32_t so = (uint32_t)c4 * 4096 + sw_off(row, unit);
                CP_ASYNC16(sQh + so, qh + grow + c4 * 32);
            }
        }
#pragma unroll
        for (int p = 0; p < 2; p++) {
            const int row = rr + p * 32;
            const size_t g0 = (size_t)(bb * SEQ + row) * EMB + hcol + unit * 8;
#pragma unroll
            for (int c4 = 0; c4 < 4; c4++) {
                const uint32_t so = (uint32_t)c4 * 4096 + sw_off(row, unit);
                CP_ASYNC16(sKV + so,         kh + g0 + c4 * 32);
                CP_ASYNC16(sKV + 16384 + so, vh + g0 + c4 * 32);
            }
        }
        CP_COMMIT();
    }

    float o[16][4];
#pragma unroll
    for (int j = 0; j < 16; j++)
#pragma unroll
        for (int c = 0; c < 4; c++) o[j][c] = 0.0f;
    float m0 = -1e30f, m1 = -1e30f, l0 = 0.0f, l1 = 0.0f;

    uint32_t qa[8][4];                   // Q fragments, loop-invariant

    int rb = 0, rbn = 1;                 // ring slot of kb, kb+1
    for (int kb = 0; kb < nkb; kb++) {
        const uint32_t buf = sKV + (uint32_t)rb * FL_KVBUF_B;

        // Prefetch kb+1 into slot rbn (last read at iteration kb-2; the
        // __syncthreads at iterations kb-1 and kb fence all its readers).
        if (kb + 1 < nkb) {
            const uint32_t nbuf = sKV + (uint32_t)rbn * FL_KVBUF_B;
            const int unit = tid & 3;
            const int rr   = tid >> 2;
#pragma unroll
            for (int p = 0; p < 2; p++) {
                const int row = rr + p * 32;
                const size_t grow = (size_t)(bb * SEQ + (kb + 1) * 64 + row) * EMB + hcol + unit * 8;
#pragma unroll
                for (int c4 = 0; c4 < 4; c4++) {
                    const uint32_t so = (uint32_t)c4 * 4096 + sw_off(row, unit);
                    CP_ASYNC16(nbuf + so,         kh + grow + c4 * 32);
                    CP_ASYNC16(nbuf + 16384 + so, vh + grow + c4 * 32);
                }
            }
        }
        CP_COMMIT();
        CP_WAIT1();
        __syncthreads();

        if (kb == 0) {
            // Load Q fragments once; reused for the entire KV loop.
#pragma unroll
            for (int ks = 0; ks < 8; ks++) {
                const uint32_t qoff = (uint32_t)(ks >> 1) * 4096 +
                                      sw_off(wm16 + lrow, (ks & 1) * 2 + lch);
                LDSM4(qa[ks], sQh + qoff);
            }
        }

        {
            float s[8][4];
#pragma unroll
            for (int j = 0; j < 8; j++)
#pragma unroll
                for (int c = 0; c < 4; c++) s[j][c] = 0.0f;

            // ---- S = Q K^T (fp16, Q frags cached) ----
#pragma unroll
            for (int ks = 0; ks < 8; ks++) {
                uint32_t kbh[4][4];
#pragma unroll
                for (int g = 0; g < 4; g++) {
                    const uint32_t koff = (uint32_t)(ks >> 1) * 4096 +
                                          sw_off(g * 16 + lrow, (ks & 1) * 2 + lch);
                    LDSM4(kbh[g], buf + koff);
                }
#pragma unroll
                for (int g = 0; g < 4; g++)
#pragma unroll
                    for (int h = 0; h < 2; h++)
                        MMA16816(s[g * 2 + h], qa[ks], kbh[g][h], kbh[g][2 + h]);
            }

            // causal mask (scale already folded into Q)
            if (kb * 64 + 63 > q0 + wm16) {
                const int row0 = q0 + wm16 + gr;
#pragma unroll
                for (int j = 0; j < 8; j++) {
                    const int col = kb * 64 + (j >> 1) * 16 + (j & 1) * 8 + 2 * t4;
                    if (col > row0)         s[j][0] = -1e30f;
                    if (col + 1 > row0)     s[j][1] = -1e30f;
                    if (col > row0 + 8)     s[j][2] = -1e30f;
                    if (col + 1 > row0 + 8) s[j][3] = -1e30f;
                }
            }

            // ---- online softmax ----
            float mx0 = -1e30f, mx1 = -1e30f;
#pragma unroll
            for (int j = 0; j < 8; j++) {
                mx0 = fmaxf(mx0, fmaxf(s[j][0], s[j][1]));
                mx1 = fmaxf(mx1, fmaxf(s[j][2], s[j][3]));
            }
            mx0 = fmaxf(mx0, __shfl_xor_sync(0xffffffffu, mx0, 1));
            mx0 = fmaxf(mx0, __shfl_xor_sync(0xffffffffu, mx0, 2));
            mx1 = fmaxf(mx1, __shfl_xor_sync(0xffffffffu, mx1, 1));
            mx1 = fmaxf(mx1, __shfl_xor_sync(0xffffffffu, mx1, 2));

            const float mn0 = fmaxf(m0, mx0), mn1 = fmaxf(m1, mx1);
            const float a0 = __expf(m0 - mn0), a1 = __expf(m1 - mn1);
            m0 = mn0; m1 = mn1;

            float rs0 = 0.0f, rs1 = 0.0f;
#pragma unroll
            for (int j = 0; j < 8; j++) {
                s[j][0] = __expf(s[j][0] - mn0); rs0 += s[j][0];
                s[j][1] = __expf(s[j][1] - mn0); rs0 += s[j][1];
                s[j][2] = __expf(s[j][2] - mn1); rs1 += s[j][2];
                s[j][3] = __expf(s[j][3] - mn1); rs1 += s[j][3];
            }
            rs0 += __shfl_xor_sync(0xffffffffu, rs0, 1);
            rs0 += __shfl_xor_sync(0xffffffffu, rs0, 2);
            rs1 += __shfl_xor_sync(0xffffffffu, rs1, 1);
            rs1 += __shfl_xor_sync(0xffffffffu, rs1, 2);
            l0 = l0 * a0 + rs0;
            l1 = l1 * a1 + rs1;

#pragma unroll
            for (int j = 0; j < 16; j++) {
                o[j][0] *= a0; o[j][1] *= a0;
                o[j][2] *= a1; o[j][3] *= a1;
            }

            // ---- O += P V (fp16 P) ----
#pragma unroll
            for (int kk = 0; kk < 4; kk++) {
                const float* sA = s[2 * kk];
                const float* sB = s[2 * kk + 1];
                uint32_t pa_h[4];
                pa_h[0] = pack_h2(sA[0], sA[1]);
                pa_h[1] = pack_h2(sA[2], sA[3]);
                pa_h[2] = pack_h2(sB[0], sB[1]);
                pa_h[3] = pack_h2(sB[2], sB[3]);
                const int vkrow = kk * 16 + tkrow;
#pragma unroll
                for (int gp = 0; gp < 4; gp++) {
                    uint32_t vbh[2][4];
#pragma unroll
                    for (int i2 = 0; i2 < 2; i2++) {
                        const int dcol = (gp * 2 + i2) * 16 + tdh;
                        const uint32_t voff = (uint32_t)(dcol >> 5) * 4096 +
                                              sw_off(vkrow, (dcol >> 3) & 3);
                        LDSM4T(vbh[i2], buf + 16384 + voff);
                    }
#pragma unroll
                    for (int i2 = 0; i2 < 2; i2++)
#pragma unroll
                        for (int h = 0; h < 2; h++)
                            MMA16816(o[(gp * 2 + i2) * 2 + h], pa_h,
                                     vbh[i2][h], vbh[i2][2 + h]);
                }
            }
        }
        rb = rbn;
        rbn = (rbn == 2) ? 0 : rbn + 1;
    }

    // Epilogue: ctx = O / l, fp16, [B,S,E] row-major
    const float inv0 = 1.0f / l0, inv1 = 1.0f / l1;
    const int row0 = q0 + wm16 + gr;
    const size_t base0 = (size_t)(bb * SEQ + row0) * EMB + hcol;
    const size_t base1 = base0 + (size_t)8 * EMB;
#pragma unroll
    for (int j = 0; j < 16; j++) {
        const int d0 = j * 8 + 2 * t4;
        *(__half2*)(cth + base0 + d0) = __floats2half2_rn(o[j][0] * inv0, o[j][1] * inv0);
        *(__half2*)(cth + base1 + d0) = __floats2half2_rn(o[j][2] * inv1, o[j][3] * inv1);
    }
}

// ---------------------------------------------------------------------------
extern "C" void kernel_launch(void* const* d_in, const int* in_sizes, int n_in,
                              void* d_out, int out_size)
{
    const float* x  = (const float*)d_in[0];
    const float* Wq = (const float*)d_in[2];
    const float* bq = (const float*)d_in[3];
    const float* Wk = (const float*)d_in[4];
    const float* bk = (const float*)d_in[5];
    const float* Wv = (const float*)d_in[6];
    const float* bv = (const float*)d_in[7];
    const float* Wo = (const float*)d_in[8];
    const float* bo = (const float*)d_in[9];
    float* out = (float*)d_out;

    __half *xh, *wp, *qh, *kh, *vh;
    cudaGetSymbolAddress((void**)&xh, g_xh);
    cudaGetSymbolAddress((void**)&wp, g_w);
    cudaGetSymbolAddress((void**)&qh, g_qh);
    cudaGetSymbolAddress((void**)&kh, g_kh);
    cudaGetSymbolAddress((void**)&vh, g_vh);

    const int nX4 = MROWS * EMB / 4;
    const int nW4 = EMB * EMB / 4;
    const int nTot = nX4 + 4 * nW4;

    conv_all<<<(nTot + 255) / 256, 256>>>(x, Wq, Wk, Wv, Wo, xh, wp, nX4, nW4);

    cudaFuncSetAttribute(gemm_qkv, cudaFuncAttributeMaxDynamicSharedMemorySize,
                         GEMM_DSMEM);
    cudaFuncSetAttribute(gemm_oproj, cudaFuncAttributeMaxDynamicSharedMemorySize,
                         GEMM_DSMEM);

    // Fused QKV: grid.z = 3 selects projection; CTA tile 128x128
    gemm_qkv<<<dim3(EMB / 128, MROWS / 128, 3), 256, GEMM_DSMEM>>>(
        xh, wp, bq, bk, bv, qh, kh, vh);

    cudaFuncSetAttribute(flash_f16, cudaFuncAttributeMaxDynamicSharedMemorySize,
                         FL_SMEM);
    // flash writes ctx (fp16) into xh (X dead after QKV GEMMs)
    flash_f16<<<dim3(SEQ / 64, BATCH * HEADS), FL_THREADS, FL_SMEM>>>(
        qh, kh, vh, xh);

    gemm_oproj<<<dim3(EMB / 128, MROWS / 128), 256, GEMM_DSMEM>>>(
        xh, wp + 3 * (size_t)EMB * EMB, bo, out);
}